// round 1
// baseline (speedup 1.0000x reference)
#include <cuda_runtime.h>

#define B_    8
#define CI_   512
#define CO_   256
#define HW_   64
#define YP_   136      // padded y stride (y rows -1..130 live at 0..131, valid y 0..128 at +1)
#define ZS_   128
#define COT   16       // output channels per block
#define CIT   8        // input channels per smem chunk
#define QT    13       // quads per tile dim (65 = 5*13, exact fit)
#define NTH   169      // 13*13 threads, 1 quad each

__device__ float g_km[CI_ * 9 * CO_];          // modulated, flipped: [ci][tap][co]
__device__ float g_y[B_ * CO_ * YP_ * YP_];    // padded intermediate (pad stays 0 from static init)

__device__ __forceinline__ void ffma2(unsigned long long& d, unsigned long long a, unsigned long long b) {
    asm("fma.rn.f32x2 %0, %1, %2, %0;" : "+l"(d) : "l"(a), "l"(b));
}
__device__ __forceinline__ float f2lo(unsigned long long v) { return __uint_as_float((unsigned)v); }
__device__ __forceinline__ float f2hi(unsigned long long v) { return __uint_as_float((unsigned)(v >> 32)); }

// ---------------- prep: demodulate + flip weights, layout [ci][tap][co] ----------------
__global__ void prep_kernel(const float* __restrict__ w) {
    __shared__ float red[256];
    const int o = blockIdx.x, tid = threadIdx.x;
    const float wsc = 1.0f / sqrtf((float)(CI_ * 9));
    const float* wo = w + o * (CI_ * 9);
    float s = 0.f;
    for (int idx = tid; idx < CI_ * 9; idx += 256) {
        float v = wo[idx] * wsc;
        s += v * v;
    }
    red[tid] = s;
    __syncthreads();
    for (int st = 128; st > 0; st >>= 1) {
        if (tid < st) red[tid] += red[tid + st];
        __syncthreads();
    }
    const float scale = wsc * rsqrtf(red[0] + 1e-6f);
    for (int idx = tid; idx < CI_ * 9; idx += 256) {
        int i = idx / 9, t = idx % 9, kh = t / 3, kw = t % 3;
        float v = wo[i * 9 + (2 - kh) * 3 + (2 - kw)] * scale;   // spatial flip
        g_km[idx * CO_ + o] = v;                                 // idx == i*9+t
    }
}

// ---------------- transposed conv (lhs_dilation=2, pad 2), quad-decomposed ----------------
// quad (a,b) -> y[2a..2a+1][2b..2b+1] from x[a-1..a][b-1..b]:
//   y[2a  ][2b  ] += k0*x00 + k2*x01 + k6*x10 + k8*x11
//   y[2a  ][2b+1] += k1*x01 + k7*x11
//   y[2a+1][2b  ] += k3*x10 + k5*x11
//   y[2a+1][2b+1] += k4*x11
__global__ void __launch_bounds__(NTH, 2) conv_kernel(const float* __restrict__ x) {
    __shared__ float2 xs[CIT][QT + 1][QT + 2];   // x duplicated (v,v): LDS.64 feeds f32x2 directly
    __shared__ float4 wsm[CIT][9][COT / 4];      // [ci][tap][co/4]

    const int tid = threadIdx.x;
    const int bb  = blockIdx.z >> 4;
    const int co0 = (blockIdx.z & 15) * COT;
    const int A0  = blockIdx.y * QT;
    const int B0  = blockIdx.x * QT;
    const int qy  = tid / QT;
    const int qx  = tid % QT;

    unsigned long long acc[4][COT / 2];          // [pixel][co-pair] packed f32x2
#pragma unroll
    for (int p = 0; p < 4; p++)
#pragma unroll
        for (int j = 0; j < COT / 2; j++) acc[p][j] = 0ull;

    const float* xb = x + (size_t)bb * CI_ * HW_ * HW_;
    float* wsf = (float*)wsm;

    for (int cc = 0; cc < CI_; cc += CIT) {
        __syncthreads();
        // stage x tile (14x14 per ci), zero-padded at image borders
        for (int idx = tid; idx < CIT * 14 * 14; idx += NTH) {
            int ci = idx / 196, rem = idx % 196, r = rem / 14, c = rem % 14;
            int iy = A0 - 1 + r, ix = B0 - 1 + c;
            float v = 0.f;
            if ((unsigned)iy < HW_ && (unsigned)ix < HW_)
                v = xb[((cc + ci) * HW_ + iy) * HW_ + ix];
            xs[ci][r][c] = make_float2(v, v);
        }
        // stage weights (warp-uniform consumers -> LDS broadcast)
        for (int idx = tid; idx < CIT * 9 * COT; idx += NTH) {
            int ci = idx / (9 * COT), rem = idx % (9 * COT);
            int t = rem / COT, c = rem % COT;
            wsf[idx] = g_km[((cc + ci) * 9 + t) * CO_ + co0 + c];
        }
        __syncthreads();
#pragma unroll 2
        for (int ci = 0; ci < CIT; ci++) {
            unsigned long long x00 = *(const unsigned long long*)&xs[ci][qy][qx];
            unsigned long long x01 = *(const unsigned long long*)&xs[ci][qy][qx + 1];
            unsigned long long x10 = *(const unsigned long long*)&xs[ci][qy + 1][qx];
            unsigned long long x11 = *(const unsigned long long*)&xs[ci][qy + 1][qx + 1];
#pragma unroll
            for (int g = 0; g < COT / 4; g++) {
#pragma unroll
                for (int t = 0; t < 9; t++) {
                    ulonglong2 kk = *(const ulonglong2*)&wsm[ci][t][g];
                    unsigned long long xv = (t == 0) ? x00
                                          : (t == 1 || t == 2) ? x01
                                          : (t == 3 || t == 6) ? x10 : x11;
                    const int p = (t == 0 || t == 2 || t == 6 || t == 8) ? 0
                                : (t == 1 || t == 7) ? 1
                                : (t == 3 || t == 5) ? 2 : 3;
                    ffma2(acc[p][2 * g],     xv, kk.x);
                    ffma2(acc[p][2 * g + 1], xv, kk.y);
                }
            }
        }
    }

    // epilogue: write padded y (valid y rows/cols 0..128 live at +1)
    const int oy0 = 2 * (A0 + qy);
    const int ox0 = 2 * (B0 + qx);
    const bool row1 = (oy0 + 1) <= 128;
    const bool col1 = (ox0 + 1) <= 128;
    float* yb = g_y + (size_t)(bb * CO_ + co0) * (YP_ * YP_);
#pragma unroll
    for (int col = 0; col < COT; col++) {
        float* yco = yb + (size_t)col * (YP_ * YP_);
        const int cp = col >> 1;
        float v00, v01, v10, v11;
        if (col & 1) {
            v00 = f2hi(acc[0][cp]); v01 = f2hi(acc[1][cp]);
            v10 = f2hi(acc[2][cp]); v11 = f2hi(acc[3][cp]);
        } else {
            v00 = f2lo(acc[0][cp]); v01 = f2lo(acc[1][cp]);
            v10 = f2lo(acc[2][cp]); v11 = f2lo(acc[3][cp]);
        }
        int base = (oy0 + 1) * YP_ + (ox0 + 1);
        yco[base] = v00;
        if (col1) yco[base + 1] = v01;
        if (row1) yco[base + YP_] = v10;
        if (row1 && col1) yco[base + YP_ + 1] = v11;
    }
}

// ---------------- depthwise 4x4 FIR blur, pad 1, gain 4 ----------------
__global__ void blur_kernel(float* __restrict__ z) {
    const int tid = threadIdx.x;
    const int zx0 = (tid & 31) * 4;
    const int zy  = blockIdx.y * 8 + (tid >> 5);
    const int bc  = blockIdx.z;
    const float* yb = g_y + (size_t)bc * (YP_ * YP_);
    float r0 = 0.f, r1 = 0.f, r2 = 0.f, r3 = 0.f;
#pragma unroll
    for (int m = 0; m < 4; m++) {
        const float* row = yb + (zy + m) * YP_ + zx0;   // ypad row zy+m == y row zy+m-1
        float4 a = *(const float4*)row;
        float4 b = *(const float4*)(row + 4);
        float fm = (m == 1 || m == 2) ? 3.f : 1.f;
        r0 += fm * (a.x + 3.f * a.y + 3.f * a.z + a.w);
        r1 += fm * (a.y + 3.f * a.z + 3.f * a.w + b.x);
        r2 += fm * (a.z + 3.f * a.w + 3.f * b.x + b.y);
        r3 += fm * (a.w + 3.f * b.x + 3.f * b.y + b.z);
    }
    float4 out = make_float4(r0 * 0.0625f, r1 * 0.0625f, r2 * 0.0625f, r3 * 0.0625f);
    *(float4*)&z[((size_t)bc * ZS_ + zy) * ZS_ + zx0] = out;
}

extern "C" void kernel_launch(void* const* d_in, const int* in_sizes, int n_in,
                              void* d_out, int out_size) {
    const float* x = (const float*)d_in[0];
    const float* w = (const float*)d_in[1];
    float* z = (float*)d_out;
    prep_kernel<<<CO_, 256>>>(w);
    conv_kernel<<<dim3(5, 5, B_ * (CO_ / COT)), NTH>>>(x);
    blur_kernel<<<dim3(1, ZS_ / 8, B_ * CO_), 256>>>(z);
}